// round 3
// baseline (speedup 1.0000x reference)
#include <cuda_runtime.h>
#include <cstdint>

#define BATCH 16
#define CIN   256
#define COUT  256
#define HH    64
#define WW    64
#define LAT   512

// ---------------- scratch (device globals; no allocation) ----------------
__device__ __align__(16) float g_s[BATCH * CIN];              // style scales
__device__ __align__(16) float g_d[BATCH * COUT];             // demod scales
__device__ __align__(16) float g_wssT[CIN * COUT];            // sum_kk w^2, [ci][co]
__device__ __align__(16) float g_wT[CIN * 9 * COUT];          // weight transposed [ci*9+t][co]
__device__ __align__(16) float g_wmod[BATCH * CIN * 9 * COUT];// modulated [b][ci*9+t][co]

// ---------------- prep kernels ----------------

// s[b][c] = style[b] . style_w[:,c] + style_b[c]
__global__ void style_kernel(const float* __restrict__ style,
                             const float* __restrict__ style_w,
                             const float* __restrict__ style_b) {
    __shared__ float st[LAT];
    int b = blockIdx.x, tid = threadIdx.x;
    st[tid]       = style[b * LAT + tid];
    st[tid + 256] = style[b * LAT + tid + 256];
    __syncthreads();
    float acc = style_b[tid];
#pragma unroll 8
    for (int l = 0; l < LAT; l++) acc += st[l] * style_w[l * CIN + tid];
    g_s[b * CIN + tid] = acc;
}

// wssT[ci][co] = sum_t weight[co][ci][t]^2
__global__ void wss_kernel(const float* __restrict__ weight) {
    int ci = blockIdx.x, co = threadIdx.x;
    const float* wp = weight + co * (CIN * 9) + ci * 9;
    float s = 0.f;
#pragma unroll
    for (int t = 0; t < 9; t++) { float v = wp[t]; s += v * v; }
    g_wssT[ci * COUT + co] = s;
}

// d[b][co] = rsqrt( sum_ci wssT[ci][co] * s[b][ci]^2 + eps )
__global__ void d_kernel() {
    __shared__ float s2[CIN];
    int b = blockIdx.x, co = threadIdx.x;
    float sv = g_s[b * CIN + co];
    s2[co] = sv * sv;
    __syncthreads();
    float acc = 1e-8f;
#pragma unroll 8
    for (int ci = 0; ci < CIN; ci++) acc += g_wssT[ci * COUT + co] * s2[ci];
    g_d[b * COUT + co] = rsqrtf(acc);
}

// transpose weight: wT[row=ci*9+t][co] = weight[co][row]
__global__ void wt_kernel(const float* __restrict__ weight) {
    int o = blockIdx.x * 256 + threadIdx.x;   // 589824 total
    int co = o & 255;
    int row = o >> 8;                          // 0..2303
    g_wT[row * COUT + co] = weight[co * (CIN * 9) + row];
}

// wmod[b][row][co] = wT[row][co] * s[b][ci] * d[b][co]
__global__ void wmod_kernel() {
    int o = blockIdx.x * 256 + threadIdx.x;   // 9437184 total
    int co = o & 255;
    int r = o >> 8;                            // b*2304 + row
    int b = r / 2304;
    int row = r - b * 2304;
    int ci = row / 9;
    g_wmod[o] = g_wT[row * COUT + co] * g_s[b * CIN + ci] * g_d[b * COUT + co];
}

// ---------------- main conv kernel ----------------

#define CCH 16                     // cin chunk
#define COT 64                     // cout tile per block
#define XP  20                     // xs row pitch (floats)
#define XS_FLOATS (CCH * 18 * XP)  // 5760
#define WS_FLOATS (CCH * 9 * COT)  // 9216
#define SMEM_BYTES ((XS_FLOATS + WS_FLOATS) * 4)  // 59904

// packed f32x2 fma: d = a*b + d  (sm_100+ FFMA2 path, per B300 docs)
#define FMA2(d, a, b) \
    asm("fma.rn.f32x2 %0, %1, %2, %0;" : "+l"(d) : "l"(a), "l"(b))
#define PACK2(out, v) \
    asm("mov.b64 %0, {%1, %1};" : "=l"(out) : "r"(__float_as_uint(v)))
#define UNPACK2(lo, hi, in) \
    asm("mov.b64 {%0, %1}, %2;" : "=r"(lo), "=r"(hi) : "l"(in))

__global__ void __launch_bounds__(256, 2)
conv_kernel(const float* __restrict__ x, const float* __restrict__ noise,
            const float* __restrict__ bias, const float* __restrict__ nwptr,
            float* __restrict__ out) {
    extern __shared__ float smem[];
    float* xs = smem;                  // [CCH][18][XP]
    float* ws = smem + XS_FLOATS;      // [CCH*9][COT]

    const int b = blockIdx.z;
    const int coutBase = blockIdx.y * COT;
    const int tY = blockIdx.x >> 2, tX = blockIdx.x & 3;
    const int oy0 = tY * 16, ox0 = tX * 16;
    const int tid = threadIdx.x;
    const int g = tid >> 6;             // cout group 0..3 (16 couts each)
    const int s = tid & 63;             // strip id
    const int ty = s >> 2;              // 0..15
    const int tx0 = (s & 3) << 2;       // 0,4,8,12

    uint64_t acc[8][4];                 // [cout-pair][pixel], 64 fp32 total
#pragma unroll
    for (int j = 0; j < 8; j++)
#pragma unroll
        for (int p = 0; p < 4; p++) acc[j][p] = 0ull;

    const float* xb_g = x + (size_t)(b * CIN) * (HH * WW);

    for (int cb = 0; cb < CIN; cb += CCH) {
        __syncthreads();
        // ---- load x halo tile: 16ci x 18 x 18 (zero padded)
        for (int idx = tid; idx < CCH * 18 * 18; idx += 256) {
            int ci = idx / 324;
            int r = idx - ci * 324;
            int ry = r / 18;
            int rx = r - ry * 18;
            int iy = oy0 - 1 + ry;
            int ix = ox0 - 1 + rx;
            float v = 0.f;
            if ((unsigned)iy < HH && (unsigned)ix < WW)
                v = xb_g[(cb + ci) * (HH * WW) + iy * WW + ix];
            xs[(ci * 18 + ry) * XP + rx] = v;
        }
        // ---- load modulated weights: [row=ci*9+t][co 0..63], coalesced float4
        const float* wsrc = g_wmod + (size_t)(b * 2304 + cb * 9) * COUT + coutBase;
        for (int e = tid; e < 2304; e += 256) {     // exactly 9 iters
            int row = e >> 4;
            int c4 = (e & 15) << 2;
            *(float4*)&ws[row * COT + c4] = *(const float4*)(wsrc + row * COUT + c4);
        }
        __syncthreads();

        for (int ci = 0; ci < CCH; ci++) {
            const float* xrow0 = &xs[(ci * 18 + ty) * XP + tx0];
#pragma unroll
            for (int ky = 0; ky < 3; ky++) {
                const float* xr = xrow0 + ky * XP;
                float4 xa = *(const float4*)xr;
                float2 xc = *(const float2*)(xr + 4);
                uint64_t xp[6];
                PACK2(xp[0], xa.x); PACK2(xp[1], xa.y);
                PACK2(xp[2], xa.z); PACK2(xp[3], xa.w);
                PACK2(xp[4], xc.x); PACK2(xp[5], xc.y);
#pragma unroll
                for (int kx = 0; kx < 3; kx++) {
                    const ulonglong2* wq =
                        (const ulonglong2*)&ws[(ci * 9 + ky * 3 + kx) * COT + g * 16];
                    ulonglong2 a0 = wq[0], a1 = wq[1], a2 = wq[2], a3 = wq[3];
                    uint64_t wp[8] = {a0.x, a0.y, a1.x, a1.y, a2.x, a2.y, a3.x, a3.y};
#pragma unroll
                    for (int p = 0; p < 4; p++) {
                        uint64_t xx = xp[kx + p];
#pragma unroll
                        for (int j = 0; j < 8; j++)
                            FMA2(acc[j][p], wp[j], xx);
                    }
                }
            }
        }
    }

    // ---- epilogue: noise + bias + leaky_relu * sqrt(2)
    const int oy = oy0 + ty;
    const int ox = ox0 + tx0;
    const float nw = nwptr[0];
    float4 nz = *(const float4*)&noise[b * (HH * WW) + oy * WW + ox];
    float nzv[4] = {nz.x * nw, nz.y * nw, nz.z * nw, nz.w * nw};
#pragma unroll
    for (int j = 0; j < 8; j++) {
        int co0 = coutBase + g * 16 + j * 2;
        float b0 = bias[co0], b1 = bias[co0 + 1];
        float4 o0, o1;
#pragma unroll
        for (int p = 0; p < 4; p++) {
            unsigned ulo, uhi;
            UNPACK2(ulo, uhi, acc[j][p]);
            float v0 = __uint_as_float(ulo) + nzv[p] + b0;
            v0 = (v0 > 0.f ? v0 : 0.2f * v0) * 1.41421356237309515f;
            float v1 = __uint_as_float(uhi) + nzv[p] + b1;
            v1 = (v1 > 0.f ? v1 : 0.2f * v1) * 1.41421356237309515f;
            ((float*)&o0)[p] = v0;
            ((float*)&o1)[p] = v1;
        }
        *(float4*)&out[((size_t)(b * COUT + co0) * HH + oy) * WW + ox] = o0;
        *(float4*)&out[((size_t)(b * COUT + co0 + 1) * HH + oy) * WW + ox] = o1;
    }
}

// ---------------- launch ----------------
extern "C" void kernel_launch(void* const* d_in, const int* in_sizes, int n_in,
                              void* d_out, int out_size) {
    const float* x        = (const float*)d_in[0];
    const float* style    = (const float*)d_in[1];
    const float* noise    = (const float*)d_in[2];
    const float* weight   = (const float*)d_in[3];
    const float* style_w  = (const float*)d_in[4];
    const float* style_b  = (const float*)d_in[5];
    const float* bias     = (const float*)d_in[6];
    const float* nw       = (const float*)d_in[7];
    float* out = (float*)d_out;

    cudaFuncSetAttribute(conv_kernel, cudaFuncAttributeMaxDynamicSharedMemorySize,
                         SMEM_BYTES);

    style_kernel<<<BATCH, 256>>>(style, style_w, style_b);
    wss_kernel<<<CIN, 256>>>(weight);
    d_kernel<<<BATCH, 256>>>();
    wt_kernel<<<(CIN * 9 * COUT) / 256, 256>>>(weight);
    wmod_kernel<<<(BATCH * CIN * 9 * COUT) / 256, 256>>>();
    conv_kernel<<<dim3(16, 4, 16), 256, SMEM_BYTES>>>(x, noise, bias, nw, out);
}

// round 5
// speedup vs baseline: 2.2916x; 2.2916x over previous
#include <cuda_runtime.h>
#include <cstdint>

#define BATCH 16
#define CIN   256
#define COUT  256
#define HH    64
#define WW    64
#define LAT   512
#define KTOT  2304   // 9*256, k = cig*288 + tap*32 + cil

// ---------------- scratch (device globals; no allocation) ----------------
__device__ __align__(16) float g_s[BATCH * CIN];
__device__ __align__(16) float g_d[BATCH * COUT];
__device__ __align__(16) float g_wss[CIN * COUT];
// A panels: [b][coTile(2)][k(2304)][m(128)], tf32-rounded
__device__ __align__(16) float g_wA[(size_t)BATCH * 2 * KTOT * 128];

__device__ __forceinline__ uint32_t tf32_rna(float v) {
    uint32_t u;
    asm("cvt.rna.tf32.f32 %0, %1;" : "=r"(u) : "f"(v));
    return u;
}

// ---------------- prep kernels ----------------
__global__ void style_kernel(const float* __restrict__ style,
                             const float* __restrict__ style_w,
                             const float* __restrict__ style_b) {
    __shared__ float st[LAT];
    int b = blockIdx.x, tid = threadIdx.x;
    st[tid]       = style[b * LAT + tid];
    st[tid + 256] = style[b * LAT + tid + 256];
    __syncthreads();
    float acc = style_b[tid];
#pragma unroll 8
    for (int l = 0; l < LAT; l++) acc += st[l] * style_w[l * CIN + tid];
    g_s[b * CIN + tid] = acc;
}

__global__ void wss_kernel(const float* __restrict__ weight) {
    int ci = blockIdx.x, co = threadIdx.x;
    const float* wp = weight + co * (CIN * 9) + ci * 9;
    float s = 0.f;
#pragma unroll
    for (int t = 0; t < 9; t++) { float v = wp[t]; s += v * v; }
    g_wss[ci * COUT + co] = s;
}

__global__ void d_kernel() {
    __shared__ float s2[CIN];
    int b = blockIdx.x, co = threadIdx.x;
    float sv = g_s[b * CIN + co];
    s2[co] = sv * sv;
    __syncthreads();
    float acc = 1e-8f;
#pragma unroll 8
    for (int ci = 0; ci < CIN; ci++) acc += g_wss[ci * COUT + co] * s2[ci];
    g_d[b * COUT + co] = rsqrtf(acc);
}

// g_wA[b][cot][k][m] = tf32( weight[co][ci][tap] * s[b][ci] * d[b][co] )
// co = cot*128+m ; k = cig*288 + tap*32 + cil ; ci = cig*32+cil
__global__ void wa_kernel(const float* __restrict__ weight, int half) {
    int o = (half * 18432 + blockIdx.x) * 256 + threadIdx.x;
    int b  = o / 589824;
    int r  = o - b * 589824;
    int cot = r / 294912;
    int r2  = r - cot * 294912;
    int k = r2 >> 7;
    int m = r2 & 127;
    int cig = k / 288;
    int rem = k - cig * 288;
    int tap = rem >> 5;
    int cil = rem & 31;
    int ci  = cig * 32 + cil;
    int co  = cot * 128 + m;
    float v = weight[(co * CIN + ci) * 9 + tap] * g_s[b * CIN + ci] * g_d[b * COUT + co];
    g_wA[o] = __uint_as_float(tf32_rna(v));
}

// ---------------- main mma.sync tf32 implicit-GEMM conv ----------------
// CTA: M=128 co x N=128 px (2 rows). 8 warps (2x4), warp = 64x32.
// smem tiles [k=32][pitch=136] floats; pitch%32==8 -> conflict-free frag LDS.
#define PITCH 136
#define TILE_FLOATS (32 * PITCH)              // 4352
#define SMEM_FLOATS (2 * TILE_FLOATS)         // A + B = 34816 B total

#define MMA_TF32(c, a, bb)                                                     \
    asm volatile("mma.sync.aligned.m16n8k8.row.col.f32.tf32.tf32.f32 "         \
        "{%0,%1,%2,%3}, {%4,%5,%6,%7}, {%8,%9}, {%0,%1,%2,%3};"                \
        : "+f"((c)[0]), "+f"((c)[1]), "+f"((c)[2]), "+f"((c)[3])               \
        : "r"((a)[0]), "r"((a)[1]), "r"((a)[2]), "r"((a)[3]),                  \
          "r"((bb)[0]), "r"((bb)[1]))

__global__ void __launch_bounds__(256, 2)
conv_mma(const float* __restrict__ x, const float* __restrict__ noise,
         const float* __restrict__ bias, const float* __restrict__ nwptr,
         float* __restrict__ out) {
    extern __shared__ __align__(16) float smem[];
    float* As = smem;                       // [32][PITCH]
    float* Bs = smem + TILE_FLOATS;         // [32][PITCH]
    uint32_t* Asu = (uint32_t*)As;
    uint32_t* Bsu = (uint32_t*)Bs;

    const int tid  = threadIdx.x;
    const int w    = tid >> 5;
    const int lane = tid & 31;
    const int g    = lane >> 2;             // groupID 0..7
    const int tig  = lane & 3;              // thread-in-group 0..3
    const int wm   = w >> 2;                // 0..1  (64 M rows each)
    const int wn   = w & 3;                 // 0..3  (32 N cols each)

    const int y0     = blockIdx.x * 2;      // 2 image rows per CTA
    const int coBase = blockIdx.y * 128;
    const int b      = blockIdx.z;

    const float* xb = x + (size_t)b * (CIN * HH * WW);
    const float* wa = g_wA + ((size_t)b * 2 + blockIdx.y) * (KTOT * 128);

    float c[4][4][4];
#pragma unroll
    for (int mt = 0; mt < 4; mt++)
#pragma unroll
        for (int nt = 0; nt < 4; nt++)
#pragma unroll
            for (int i = 0; i < 4; i++) c[mt][nt][i] = 0.f;

    int cig = 0, tap = 0;
    for (int chunk = 0; chunk < 72; chunk++) {
        __syncthreads();
        // ---- A tile: linear copy 32k x 128m (coalesced LDG.128 -> STS.128)
        {
            const float* src = wa + chunk * (32 * 128);
#pragma unroll
            for (int i = 0; i < 4; i++) {
                int off4 = (tid + 256 * i) * 4;
                int k = off4 >> 7;
                int m = off4 & 127;
                *(float4*)&As[k * PITCH + m] = *(const float4*)(src + off4);
            }
        }
        // ---- B tile: im2col 32k x 128n, lane-consecutive n
        {
            const int ky = tap / 3;
            const int kx = tap - ky * 3;
#pragma unroll
            for (int kki = 0; kki < 4; kki++) {
                int kk = w + kki * 8;
                const float* xp = xb + (size_t)(cig * 32 + kk) * (HH * WW);
#pragma unroll
                for (int ng = 0; ng < 4; ng++) {
                    int n  = ng * 32 + lane;
                    int yy = y0 + (n >> 6) + ky - 1;
                    int xx = (n & 63) + kx - 1;
                    uint32_t v = 0;
                    if ((unsigned)yy < HH && (unsigned)xx < WW)
                        v = tf32_rna(xp[yy * WW + xx]);
                    Bsu[kk * PITCH + n] = v;
                }
            }
        }
        __syncthreads();

        // ---- compute: 4 k-steps of m16n8k8
#pragma unroll
        for (int ks = 0; ks < 4; ks++) {
            const uint32_t* Ak  = Asu + (ks * 8 + tig) * PITCH;
            const uint32_t* Ak4 = Ak + 4 * PITCH;
            uint32_t a[4][4];
#pragma unroll
            for (int mt = 0; mt < 4; mt++) {
                int m0 = wm * 64 + mt * 16 + g;
                a[mt][0] = Ak[m0];
                a[mt][1] = Ak[m0 + 8];
                a[mt][2] = Ak4[m0];
                a[mt][3] = Ak4[m0 + 8];
            }
            const uint32_t* Bk  = Bsu + (ks * 8 + tig) * PITCH;
            const uint32_t* Bk4 = Bk + 4 * PITCH;
            uint32_t bb[4][2];
#pragma unroll
            for (int nt = 0; nt < 4; nt++) {
                int n0 = wn * 32 + nt * 8 + g;
                bb[nt][0] = Bk[n0];
                bb[nt][1] = Bk4[n0];
            }
#pragma unroll
            for (int mt = 0; mt < 4; mt++)
#pragma unroll
                for (int nt = 0; nt < 4; nt++)
                    MMA_TF32(c[mt][nt], a[mt], bb[nt]);
        }

        if (++tap == 9) { tap = 0; ++cig; }
    }

    // ---- epilogue: noise + bias + leaky_relu * sqrt(2)
    {
        const float nw = nwptr[0];
        const int y = y0 + (wn >> 1);               // row fixed per warp
        const float* nzrow = noise + (size_t)b * (HH * WW) + y * WW;
#pragma unroll
        for (int mt = 0; mt < 4; mt++) {
            int co0 = coBase + wm * 64 + mt * 16 + g;
            float bv0 = bias[co0];
            float bv1 = bias[co0 + 8];
            float* o0 = out + (size_t)(b * COUT + co0) * (HH * WW) + y * WW;
            float* o1 = o0 + 8 * (HH * WW);
#pragma unroll
            for (int nt = 0; nt < 4; nt++) {
                int xc = (wn & 1) * 32 + nt * 8 + tig * 2;
                float2 nz = *(const float2*)(nzrow + xc);
                float nzx = nz.x * nw, nzy = nz.y * nw;
                float v0 = c[mt][nt][0] + nzx + bv0;
                float v1 = c[mt][nt][1] + nzy + bv0;
                float v2 = c[mt][nt][2] + nzx + bv1;
                float v3 = c[mt][nt][3] + nzy + bv1;
                v0 = (v0 > 0.f ? v0 : 0.2f * v0) * 1.41421356237309515f;
                v1 = (v1 > 0.f ? v1 : 0.2f * v1) * 1.41421356237309515f;
                v2 = (v2 > 0.f ? v2 : 0.2f * v2) * 1.41421356237309515f;
                v3 = (v3 > 0.f ? v3 : 0.2f * v3) * 1.41421356237309515f;
                *(float2*)(o0 + xc) = make_float2(v0, v1);
                *(float2*)(o1 + xc) = make_float2(v2, v3);
            }
        }
    }
}

// ---------------- launch ----------------
extern "C" void kernel_launch(void* const* d_in, const int* in_sizes, int n_in,
                              void* d_out, int out_size) {
    const float* x        = (const float*)d_in[0];
    const float* style    = (const float*)d_in[1];
    const float* noise    = (const float*)d_in[2];
    const float* weight   = (const float*)d_in[3];
    const float* style_w  = (const float*)d_in[4];
    const float* style_b  = (const float*)d_in[5];
    const float* bias     = (const float*)d_in[6];
    const float* nw       = (const float*)d_in[7];
    float* out = (float*)d_out;

    style_kernel<<<BATCH, 256>>>(style, style_w, style_b);   // launch 0
    wss_kernel<<<CIN, 256>>>(weight);                        // launch 1
    d_kernel<<<BATCH, 256>>>();                              // launch 2
    wa_kernel<<<18432, 256>>>(weight, 0);                    // launch 3
    wa_kernel<<<18432, 256>>>(weight, 1);                    // launch 4
    conv_mma<<<dim3(32, 2, 16), 256, SMEM_FLOATS * 4>>>(x, noise, bias, nw, out);  // launch 5
}

// round 6
// speedup vs baseline: 2.7517x; 1.2008x over previous
#include <cuda_runtime.h>
#include <cstdint>

#define BATCH 16
#define CIN   256
#define COUT  256
#define HH    64
#define WW    64
#define LAT   512
#define KTOT  2304   // 9*256, k = cig*288 + tap*32 + cil

// ---------------- scratch (device globals; no allocation) ----------------
__device__ __align__(16) float g_s[BATCH * CIN];
__device__ __align__(16) float g_d[BATCH * COUT];
__device__ __align__(16) float g_wss[CIN * COUT];
// A panels, fragment-major: [b][cot][chunk(72)][ks(4)][wm(2)][mt(4)][lane(32)] float4
__device__ __align__(16) float g_wA[(size_t)BATCH * 2 * KTOT * 128];

__device__ __forceinline__ uint32_t tf32_rna(float v) {
    uint32_t u;
    asm("cvt.rna.tf32.f32 %0, %1;" : "=r"(u) : "f"(v));
    return u;
}

// ---------------- prep kernels ----------------
__global__ void style_kernel(const float* __restrict__ style,
                             const float* __restrict__ style_w,
                             const float* __restrict__ style_b) {
    __shared__ float st[LAT];
    int b = blockIdx.x, tid = threadIdx.x;
    st[tid]       = style[b * LAT + tid];
    st[tid + 256] = style[b * LAT + tid + 256];
    __syncthreads();
    float acc = style_b[tid];
#pragma unroll 8
    for (int l = 0; l < LAT; l++) acc += st[l] * style_w[l * CIN + tid];
    g_s[b * CIN + tid] = acc;
}

__global__ void wss_kernel(const float* __restrict__ weight) {
    int ci = blockIdx.x, co = threadIdx.x;
    const float* wp = weight + co * (CIN * 9) + ci * 9;
    float s = 0.f;
#pragma unroll
    for (int t = 0; t < 9; t++) { float v = wp[t]; s += v * v; }
    g_wss[ci * COUT + co] = s;
}

__global__ void d_kernel() {
    __shared__ float s2[CIN];
    int b = blockIdx.x, co = threadIdx.x;
    float sv = g_s[b * CIN + co];
    s2[co] = sv * sv;
    __syncthreads();
    float acc = 1e-8f;
#pragma unroll 8
    for (int ci = 0; ci < CIN; ci++) acc += g_wss[ci * COUT + co] * s2[ci];
    g_d[b * COUT + co] = rsqrtf(acc);
}

// Fragment-major modulated weights. Each thread emits one float4 =
// {w(k,m), w(k,m+8), w(k+4,m), w(k+4,m+8)} * s * d, tf32-rounded.
__global__ void wa_kernel(const float* __restrict__ weight) {
    int o = blockIdx.x * 256 + threadIdx.x;    // float4 index, 2359296 total
    int lane = o & 31; int t = o >> 5;
    int mt = t & 3;  t >>= 2;
    int wm = t & 1;  t >>= 1;
    int ks = t & 3;  t >>= 2;
    int chunk = t % 72; t /= 72;
    int cot = t & 1; int b = t >> 1;
    int g = lane >> 2, tig = lane & 3;
    int kk  = ks * 8 + tig;                    // cil, and cil+4 for hi pair
    int cig = chunk / 9, tap = chunk - 9 * cig;
    int ci  = cig * 32 + kk;
    int co  = cot * 128 + wm * 64 + mt * 16 + g;
    float s0 = g_s[b * CIN + ci],      s1 = g_s[b * CIN + ci + 4];
    float d0 = g_d[b * COUT + co],     d1 = g_d[b * COUT + co + 8];
    float v00 = weight[(co * CIN + ci) * 9 + tap]           * s0 * d0;
    float v01 = weight[((co + 8) * CIN + ci) * 9 + tap]     * s0 * d1;
    float v10 = weight[(co * CIN + ci + 4) * 9 + tap]       * s1 * d0;
    float v11 = weight[((co + 8) * CIN + ci + 4) * 9 + tap] * s1 * d1;
    float4 r;
    r.x = __uint_as_float(tf32_rna(v00));
    r.y = __uint_as_float(tf32_rna(v01));
    r.z = __uint_as_float(tf32_rna(v10));
    r.w = __uint_as_float(tf32_rna(v11));
    ((float4*)g_wA)[o] = r;
}

// ---------------- main pipelined mma.sync tf32 implicit-GEMM ----------------
// CTA: M=128 co x N=128 px (2 rows). 8 warps (2x4), warp tile 64x32.
// 3-stage cp.async pipeline. A smem fragment-major (LDS.128), B uint2 pairs.
#define BP_U2 132                               // B row pitch in uint2 (conflict-free)
#define A_STAGE 16384
#define B_STAGE (16 * BP_U2 * 8)                // 16896
#define STAGE_BYTES (A_STAGE + B_STAGE)         // 33280
#define SMEM_BYTES (3 * STAGE_BYTES)            // 99840

#define CP16_CG(dst, src) \
    asm volatile("cp.async.cg.shared.global [%0], [%1], 16;" :: "r"(dst), "l"(src))
#define CP4_CA_Z(dst, src, sz) \
    asm volatile("cp.async.ca.shared.global [%0], [%1], 4, %2;" :: "r"(dst), "l"(src), "r"(sz))
#define CP_COMMIT() asm volatile("cp.async.commit_group;" ::: "memory")

#define MMA_TF32(c, a, b0, b1)                                                 \
    asm volatile("mma.sync.aligned.m16n8k8.row.col.f32.tf32.tf32.f32 "         \
        "{%0,%1,%2,%3}, {%4,%5,%6,%7}, {%8,%9}, {%0,%1,%2,%3};"                \
        : "+f"((c)[0]), "+f"((c)[1]), "+f"((c)[2]), "+f"((c)[3])               \
        : "r"((a).x), "r"((a).y), "r"((a).z), "r"((a).w), "r"(b0), "r"(b1))

__global__ void __launch_bounds__(256, 2)
conv_mma(const float* __restrict__ x, const float* __restrict__ noise,
         const float* __restrict__ bias, const float* __restrict__ nwptr,
         float* __restrict__ out) {
    extern __shared__ __align__(16) char smem[];
    const uint32_t sbase = (uint32_t)__cvta_generic_to_shared(smem);

    const int tid  = threadIdx.x;
    const int w    = tid >> 5;
    const int lane = tid & 31;
    const int g    = lane >> 2;
    const int tig  = lane & 3;
    const int wm   = w >> 2;
    const int wn   = w & 3;

    const int y0     = blockIdx.x * 2;
    const int coBase = blockIdx.y * 128;
    const int b      = blockIdx.z;

    const float*  xb  = x + (size_t)b * (CIN * HH * WW);
    const float4* wa4 = (const float4*)g_wA + ((size_t)(b * 2 + blockIdx.y)) * (72 * 1024);

    float c[4][4][4];
#pragma unroll
    for (int mt = 0; mt < 4; mt++)
#pragma unroll
        for (int nt = 0; nt < 4; nt++)
#pragma unroll
            for (int i = 0; i < 4; i++) c[mt][nt][i] = 0.f;

    // --- async stage loader: A (4x16B) + B im2col (16x4B, zero-filled halo)
    auto load_stage = [&](int chunk, int s) {
        const uint32_t abase = sbase + s * STAGE_BYTES;
        const uint32_t bbase = abase + A_STAGE;
        const float4* src4 = wa4 + chunk * 1024;
#pragma unroll
        for (int i = 0; i < 4; i++) {
            int idx = tid + 256 * i;
            CP16_CG(abase + idx * 16, src4 + idx);
        }
        const int cig = chunk / 9;
        const int tap = chunk - 9 * cig;
        const int ky = tap / 3;
        const int kx = tap - ky * 3;
        const uint32_t brow = bbase + ((w & 3) * BP_U2) * 8 + (w >> 2) * 4;
#pragma unroll
        for (int kki = 0; kki < 4; kki++) {
            const float* xp = xb + (size_t)(cig * 32 + w + kki * 8) * (HH * WW);
            uint32_t dr = brow + (kki * 4 * BP_U2) * 8;
#pragma unroll
            for (int ng = 0; ng < 4; ng++) {
                int n  = ng * 32 + lane;
                int yy = y0 + (n >> 6) + ky - 1;
                int xx = (n & 63) + kx - 1;
                bool ok = ((unsigned)yy < HH) && ((unsigned)xx < WW);
                const float* src = ok ? (xp + yy * WW + xx) : xp;
                CP4_CA_Z(dr + n * 8, src, ok ? 4u : 0u);
            }
        }
    };

    load_stage(0, 0); CP_COMMIT();
    load_stage(1, 1); CP_COMMIT();

    for (int chunk = 0; chunk < 72; chunk++) {
        if (chunk < 70) asm volatile("cp.async.wait_group 1;" ::: "memory");
        else            asm volatile("cp.async.wait_group 0;" ::: "memory");
        __syncthreads();
        if (chunk + 2 < 72) { load_stage(chunk + 2, (chunk + 2) % 3); CP_COMMIT(); }

        const int s = chunk % 3;
        const uint4* Af = (const uint4*)(smem + s * STAGE_BYTES);
        const uint2* Bf = (const uint2*)(smem + s * STAGE_BYTES + A_STAGE);
#pragma unroll
        for (int ks = 0; ks < 4; ks++) {
            uint4 a[4];
#pragma unroll
            for (int mt = 0; mt < 4; mt++)
                a[mt] = Af[((ks * 2 + wm) * 4 + mt) * 32 + lane];
            const uint2* Brow = Bf + (ks * 4 + tig) * BP_U2 + wn * 32 + g;
            uint2 bv[4];
#pragma unroll
            for (int nt = 0; nt < 4; nt++) bv[nt] = Brow[nt * 8];
#pragma unroll
            for (int mt = 0; mt < 4; mt++)
#pragma unroll
                for (int nt = 0; nt < 4; nt++)
                    MMA_TF32(c[mt][nt], a[mt], bv[nt].x, bv[nt].y);
        }
    }

    // ---- epilogue: noise + bias + leaky_relu * sqrt(2)
    {
        const float nw = nwptr[0];
        const int y = y0 + (wn >> 1);
        const float* nzrow = noise + (size_t)b * (HH * WW) + y * WW;
#pragma unroll
        for (int mt = 0; mt < 4; mt++) {
            int co0 = coBase + wm * 64 + mt * 16 + g;
            float bv0 = bias[co0];
            float bv1 = bias[co0 + 8];
            float* o0 = out + (size_t)(b * COUT + co0) * (HH * WW) + y * WW;
            float* o1 = o0 + 8 * (HH * WW);
#pragma unroll
            for (int nt = 0; nt < 4; nt++) {
                int xc = (wn & 1) * 32 + nt * 8 + tig * 2;
                float2 nz = *(const float2*)(nzrow + xc);
                float nzx = nz.x * nw, nzy = nz.y * nw;
                float v0 = c[mt][nt][0] + nzx + bv0;
                float v1 = c[mt][nt][1] + nzy + bv0;
                float v2 = c[mt][nt][2] + nzx + bv1;
                float v3 = c[mt][nt][3] + nzy + bv1;
                v0 = (v0 > 0.f ? v0 : 0.2f * v0) * 1.41421356237309515f;
                v1 = (v1 > 0.f ? v1 : 0.2f * v1) * 1.41421356237309515f;
                v2 = (v2 > 0.f ? v2 : 0.2f * v2) * 1.41421356237309515f;
                v3 = (v3 > 0.f ? v3 : 0.2f * v3) * 1.41421356237309515f;
                *(float2*)(o0 + xc) = make_float2(v0, v1);
                *(float2*)(o1 + xc) = make_float2(v2, v3);
            }
        }
    }
}

// ---------------- launch ----------------
extern "C" void kernel_launch(void* const* d_in, const int* in_sizes, int n_in,
                              void* d_out, int out_size) {
    const float* x        = (const float*)d_in[0];
    const float* style    = (const float*)d_in[1];
    const float* noise    = (const float*)d_in[2];
    const float* weight   = (const float*)d_in[3];
    const float* style_w  = (const float*)d_in[4];
    const float* style_b  = (const float*)d_in[5];
    const float* bias     = (const float*)d_in[6];
    const float* nw       = (const float*)d_in[7];
    float* out = (float*)d_out;

    cudaFuncSetAttribute(conv_mma, cudaFuncAttributeMaxDynamicSharedMemorySize, SMEM_BYTES);

    style_kernel<<<BATCH, 256>>>(style, style_w, style_b);   // 0
    wss_kernel<<<CIN, 256>>>(weight);                        // 1
    d_kernel<<<BATCH, 256>>>();                              // 2
    wa_kernel<<<9216, 256>>>(weight);                        // 3
    conv_mma<<<dim3(32, 2, 16), 256, SMEM_BYTES>>>(x, noise, bias, nw, out);  // 4 (+1 hidden -> ncu -s 5)
}

// round 8
// speedup vs baseline: 2.8404x; 1.0322x over previous
#include <cuda_runtime.h>
#include <cstdint>

#define BATCH 16
#define CIN   256
#define COUT  256
#define HH    64
#define WW    64
#define LAT   512
#define KTOT  2304

// ---------------- scratch (device globals; no allocation) ----------------
__device__ __align__(16) float g_s[BATCH * CIN];
__device__ __align__(16) float g_d[BATCH * COUT];
__device__ __align__(16) float g_wss[CIN * COUT];
// A panels, fragment-major: [b][cot][chunk(72)][ks(4)][wm(2)][mt(4)][lane(32)] float4
__device__ __align__(16) float g_wA[(size_t)BATCH * 2 * KTOT * 128];

__device__ __forceinline__ uint32_t tf32_rna(float v) {
    uint32_t u;
    asm("cvt.rna.tf32.f32 %0, %1;" : "=r"(u) : "f"(v));
    return u;
}

// ---------------- prep kernels (fused so conv is the 4th launch) ----------------
__global__ void fused1_kernel(const float* __restrict__ style,
                              const float* __restrict__ style_w,
                              const float* __restrict__ style_b,
                              const float* __restrict__ weight) {
    if (blockIdx.x < 16) {
        __shared__ float st[LAT];
        int b = blockIdx.x, tid = threadIdx.x;
        st[tid]       = style[b * LAT + tid];
        st[tid + 256] = style[b * LAT + tid + 256];
        __syncthreads();
        float acc = style_b[tid];
#pragma unroll 8
        for (int l = 0; l < LAT; l++) acc += st[l] * style_w[l * CIN + tid];
        g_s[b * CIN + tid] = acc;
    } else {
        int ci = blockIdx.x - 16, co = threadIdx.x;
        const float* wp = weight + co * (CIN * 9) + ci * 9;
        float s = 0.f;
#pragma unroll
        for (int t = 0; t < 9; t++) { float v = wp[t]; s += v * v; }
        g_wss[ci * COUT + co] = s;
    }
}

__global__ void d_kernel() {
    __shared__ float s2[CIN];
    int b = blockIdx.x, co = threadIdx.x;
    float sv = g_s[b * CIN + co];
    s2[co] = sv * sv;
    __syncthreads();
    float acc = 1e-8f;
#pragma unroll 8
    for (int ci = 0; ci < CIN; ci++) acc += g_wss[ci * COUT + co] * s2[ci];
    g_d[b * COUT + co] = rsqrtf(acc);
}

// Fragment-major modulated weights (validated R5 layout).
__global__ void wa_kernel(const float* __restrict__ weight) {
    int o = blockIdx.x * 256 + threadIdx.x;
    int lane = o & 31; int t = o >> 5;
    int mt = t & 3;  t >>= 2;
    int wm = t & 1;  t >>= 1;
    int ks = t & 3;  t >>= 2;
    int chunk = t % 72; t /= 72;
    int cot = t & 1; int b = t >> 1;
    int g = lane >> 2, tig = lane & 3;
    int kk  = ks * 8 + tig;
    int cig = chunk / 9, tap = chunk - 9 * cig;
    int ci  = cig * 32 + kk;
    int co  = cot * 128 + wm * 64 + mt * 16 + g;
    float s0 = g_s[b * CIN + ci],  s1 = g_s[b * CIN + ci + 4];
    float d0 = g_d[b * COUT + co], d1 = g_d[b * COUT + co + 8];
    float4 r;
    r.x = __uint_as_float(tf32_rna(weight[(co * CIN + ci) * 9 + tap]           * s0 * d0));
    r.y = __uint_as_float(tf32_rna(weight[((co + 8) * CIN + ci) * 9 + tap]     * s0 * d1));
    r.z = __uint_as_float(tf32_rna(weight[(co * CIN + ci + 4) * 9 + tap]       * s1 * d0));
    r.w = __uint_as_float(tf32_rna(weight[((co + 8) * CIN + ci + 4) * 9 + tap] * s1 * d1));
    ((float4*)g_wA)[o] = r;
}

// ---------------- main: pipelined tf32 mma.sync, tap-shift B slab ----------------
// CTA: M=128 co x N=128 px (2 rows). 8 warps (2x4), warp tile 64x32.
// A: 3-stage cp.async (fragment-major). B: one slab [32 ci][4 rows][66] per
// ci-group, reloaded every 9 chunks; taps index it with offset ky*66+kx.
#define A_STAGE   16384
#define SLAB_PITCH 264                 // 4*66 floats per ci; 264%32==8 -> frag LDS conflict-free
#define SLAB_FLOATS (32 * SLAB_PITCH)  // 8448
#define SMEM_BYTES (3 * A_STAGE + SLAB_FLOATS * 4)   // 49152 + 33792 = 82944

#define CP16_CG(dst, src) \
    asm volatile("cp.async.cg.shared.global [%0], [%1], 16;" :: "r"(dst), "l"(src))
#define CP_COMMIT() asm volatile("cp.async.commit_group;" ::: "memory")

#define MMA_TF32(c, a, b0, b1)                                                 \
    asm volatile("mma.sync.aligned.m16n8k8.row.col.f32.tf32.tf32.f32 "         \
        "{%0,%1,%2,%3}, {%4,%5,%6,%7}, {%8,%9}, {%0,%1,%2,%3};"                \
        : "+f"((c)[0]), "+f"((c)[1]), "+f"((c)[2]), "+f"((c)[3])               \
        : "r"((a).x), "r"((a).y), "r"((a).z), "r"((a).w), "r"(b0), "r"(b1))

__global__ void __launch_bounds__(256, 2)
conv_mma(const float* __restrict__ x, const float* __restrict__ noise,
         const float* __restrict__ bias, const float* __restrict__ nwptr,
         float* __restrict__ out) {
    extern __shared__ __align__(16) char smem[];
    float* slab = (float*)(smem + 3 * A_STAGE);
    const uint32_t sbase = (uint32_t)__cvta_generic_to_shared(smem);

    const int tid  = threadIdx.x;
    const int w    = tid >> 5;
    const int lane = tid & 31;
    const int g    = lane >> 2;
    const int tig  = lane & 3;
    const int wm   = w >> 2;
    const int wn   = w & 3;

    const int y0     = blockIdx.x * 2;
    const int coBase = blockIdx.y * 128;
    const int b      = blockIdx.z;

    const float*  xb  = x + (size_t)b * (CIN * HH * WW);
    const float4* wa4 = (const float4*)g_wA + ((size_t)(b * 2 + blockIdx.y)) * (72 * 1024);

    // zero slab once (pads + out-of-range rows stay zero forever)
    for (int i = tid; i < SLAB_FLOATS; i += 256) slab[i] = 0.f;

    float c[4][4][4];
#pragma unroll
    for (int mt = 0; mt < 4; mt++)
#pragma unroll
        for (int nt = 0; nt < 4; nt++)
#pragma unroll
            for (int i = 0; i < 4; i++) c[mt][nt][i] = 0.f;

    auto load_A = [&](int chunk, int s) {
        const uint32_t abase = sbase + s * A_STAGE;
        const float4* src4 = wa4 + chunk * 1024;
#pragma unroll
        for (int i = 0; i < 4; i++) {
            int idx = tid + 256 * i;
            CP16_CG(abase + idx * 16, src4 + idx);
        }
    };

    load_A(0, 0); CP_COMMIT();
    load_A(1, 1); CP_COMMIT();

    // per-thread B fragment base inside slab (excl. ks and tap terms)
    const int bfrag0 = tig * SLAB_PITCH + (wn >> 1) * 66 + (wn & 1) * 32 + g;

    for (int chunk = 0; chunk < 72; chunk++) {
        if (chunk < 70) asm volatile("cp.async.wait_group 1;" ::: "memory");
        else            asm volatile("cp.async.wait_group 0;" ::: "memory");
        __syncthreads();

        const int cig = chunk / 9;
        const int tap = chunk - 9 * cig;

        if (tap == 0) {
            // reload slab: warp w -> 16 (ci,y) rows; coalesced, conflict-free
#pragma unroll 4
            for (int rr = 0; rr < 16; rr++) {
                int row = w * 16 + rr;      // (ci,y)-pair index 0..127
                int ci  = row >> 2;
                int y   = y0 - 1 + (row & 3);
                if ((unsigned)y < HH) {
                    const float* src = xb + (size_t)(cig * 32 + ci) * (HH * WW) + y * WW;
                    float* dst = slab + ci * SLAB_PITCH + (row & 3) * 66 + 1;  // FIXED
                    dst[lane]      = src[lane];
                    dst[lane + 32] = src[lane + 32];
                }
            }
            __syncthreads();
        }

        if (chunk + 2 < 72) { load_A(chunk + 2, (chunk + 2) % 3); CP_COMMIT(); }

        const int ky = tap / 3;
        const int kx = tap - ky * 3;
        const float* bptr = slab + bfrag0 + ky * 66 + kx;
        const uint4* Af = (const uint4*)(smem + (chunk % 3) * A_STAGE);

#pragma unroll
        for (int ks = 0; ks < 4; ks++) {
            uint4 a[4];
#pragma unroll
            for (int mt = 0; mt < 4; mt++)
                a[mt] = Af[((ks * 2 + wm) * 4 + mt) * 32 + lane];
            const float* bk = bptr + ks * (8 * SLAB_PITCH);
            uint32_t b0[4], b1[4];
#pragma unroll
            for (int nt = 0; nt < 4; nt++) {
                b0[nt] = __float_as_uint(bk[nt * 8]);
                b1[nt] = __float_as_uint(bk[nt * 8 + 4 * SLAB_PITCH]);
            }
#pragma unroll
            for (int mt = 0; mt < 4; mt++)
#pragma unroll
                for (int nt = 0; nt < 4; nt++)
                    MMA_TF32(c[mt][nt], a[mt], b0[nt], b1[nt]);
        }
    }

    // ---- epilogue: noise + bias + leaky_relu * sqrt(2)
    {
        const float nw = nwptr[0];
        const int y = y0 + (wn >> 1);
        const float* nzrow = noise + (size_t)b * (HH * WW) + y * WW;
#pragma unroll
        for (int mt = 0; mt < 4; mt++) {
            int co0 = coBase + wm * 64 + mt * 16 + g;
            float bv0 = bias[co0];
            float bv1 = bias[co0 + 8];
            float* o0 = out + (size_t)(b * COUT + co0) * (HH * WW) + y * WW;
            float* o1 = o0 + 8 * (HH * WW);
#pragma unroll
            for (int nt = 0; nt < 4; nt++) {
                int xc = (wn & 1) * 32 + nt * 8 + tig * 2;
                float2 nz = *(const float2*)(nzrow + xc);
                float nzx = nz.x * nw, nzy = nz.y * nw;
                float v0 = c[mt][nt][0] + nzx + bv0;
                float v1 = c[mt][nt][1] + nzy + bv0;
                float v2 = c[mt][nt][2] + nzx + bv1;
                float v3 = c[mt][nt][3] + nzy + bv1;
                v0 = (v0 > 0.f ? v0 : 0.2f * v0) * 1.41421356237309515f;
                v1 = (v1 > 0.f ? v1 : 0.2f * v1) * 1.41421356237309515f;
                v2 = (v2 > 0.f ? v2 : 0.2f * v2) * 1.41421356237309515f;
                v3 = (v3 > 0.f ? v3 : 0.2f * v3) * 1.41421356237309515f;
                *(float2*)(o0 + xc) = make_float2(v0, v1);
                *(float2*)(o1 + xc) = make_float2(v2, v3);
            }
        }
    }
}

// ---------------- launch ----------------
extern "C" void kernel_launch(void* const* d_in, const int* in_sizes, int n_in,
                              void* d_out, int out_size) {
    const float* x        = (const float*)d_in[0];
    const float* style    = (const float*)d_in[1];
    const float* noise    = (const float*)d_in[2];
    const float* weight   = (const float*)d_in[3];
    const float* style_w  = (const float*)d_in[4];
    const float* style_b  = (const float*)d_in[5];
    const float* bias     = (const float*)d_in[6];
    const float* nw       = (const float*)d_in[7];
    float* out = (float*)d_out;

    cudaFuncSetAttribute(conv_mma, cudaFuncAttributeMaxDynamicSharedMemorySize, SMEM_BYTES);

    fused1_kernel<<<272, 256>>>(style, style_w, style_b, weight);  // launch 1
    d_kernel<<<BATCH, 256>>>();                                    // launch 2
    wa_kernel<<<9216, 256>>>(weight);                              // launch 3
    conv_mma<<<dim3(32, 2, 16), 256, SMEM_BYTES>>>(x, noise, bias, nw, out);  // launch 4
}

// round 9
// speedup vs baseline: 3.4182x; 1.2034x over previous
#include <cuda_runtime.h>
#include <cstdint>

#define BATCH 16
#define CIN   256
#define COUT  256
#define HH    64
#define WW    64
#define LAT   512
#define KTOT  2304

// ---------------- scratch (device globals; no allocation) ----------------
__device__ __align__(16) float g_s[BATCH * CIN];
__device__ __align__(16) float g_d[BATCH * COUT];
__device__ __align__(16) float g_wss[CIN * COUT];
// A panels, fragment-major: [b][cot][chunk(72)][ks(4)][wm(2)][mt(4)][lane(32)] float4
__device__ __align__(16) float g_wA[(size_t)BATCH * 2 * KTOT * 128];

__device__ __forceinline__ uint32_t tf32_rna(float v) {
    uint32_t u;
    asm("cvt.rna.tf32.f32 %0, %1;" : "=r"(u) : "f"(v));
    return u;
}

// ---------------- prep kernels ----------------
__global__ void fused1_kernel(const float* __restrict__ style,
                              const float* __restrict__ style_w,
                              const float* __restrict__ style_b,
                              const float* __restrict__ weight) {
    if (blockIdx.x < 16) {
        __shared__ float st[LAT];
        int b = blockIdx.x, tid = threadIdx.x;
        st[tid]       = style[b * LAT + tid];
        st[tid + 256] = style[b * LAT + tid + 256];
        __syncthreads();
        float acc = style_b[tid];
#pragma unroll 8
        for (int l = 0; l < LAT; l++) acc += st[l] * style_w[l * CIN + tid];
        g_s[b * CIN + tid] = acc;
    } else {
        int ci = blockIdx.x - 16, co = threadIdx.x;
        const float* wp = weight + co * (CIN * 9) + ci * 9;
        float s = 0.f;
#pragma unroll
        for (int t = 0; t < 9; t++) { float v = wp[t]; s += v * v; }
        g_wss[ci * COUT + co] = s;
    }
}

__global__ void d_kernel() {
    __shared__ float s2[CIN];
    int b = blockIdx.x, co = threadIdx.x;
    float sv = g_s[b * CIN + co];
    s2[co] = sv * sv;
    __syncthreads();
    float acc = 1e-8f;
#pragma unroll 8
    for (int ci = 0; ci < CIN; ci++) acc += g_wss[ci * COUT + co] * s2[ci];
    g_d[b * COUT + co] = rsqrtf(acc);
}

// Fragment-major modulated weights (validated R5/R8 layout).
__global__ void wa_kernel(const float* __restrict__ weight) {
    int o = blockIdx.x * 256 + threadIdx.x;
    int lane = o & 31; int t = o >> 5;
    int mt = t & 3;  t >>= 2;
    int wm = t & 1;  t >>= 1;
    int ks = t & 3;  t >>= 2;
    int chunk = t % 72; t /= 72;
    int cot = t & 1; int b = t >> 1;
    int g = lane >> 2, tig = lane & 3;
    int kk  = ks * 8 + tig;
    int cig = chunk / 9, tap = chunk - 9 * cig;
    int ci  = cig * 32 + kk;
    int co  = cot * 128 + wm * 64 + mt * 16 + g;
    float s0 = g_s[b * CIN + ci],  s1 = g_s[b * CIN + ci + 4];
    float d0 = g_d[b * COUT + co], d1 = g_d[b * COUT + co + 8];
    float4 r;
    r.x = __uint_as_float(tf32_rna(weight[(co * CIN + ci) * 9 + tap]           * s0 * d0));
    r.y = __uint_as_float(tf32_rna(weight[((co + 8) * CIN + ci) * 9 + tap]     * s0 * d1));
    r.z = __uint_as_float(tf32_rna(weight[(co * CIN + ci + 4) * 9 + tap]       * s1 * d0));
    r.w = __uint_as_float(tf32_rna(weight[((co + 8) * CIN + ci + 4) * 9 + tap] * s1 * d1));
    ((float4*)g_wA)[o] = r;
}

// ---------------- main: fully async pipelined tf32 mma.sync ----------------
// CTA: M=128 co x N=128 px (2 rows). 8 warps (2x4), warp tile 64x32.
// A: 2-stage cp.async. B: double-buffered tap-shift slab, cp.async-prefetched
// at tap==0 with 9 chunks of slack. Per-chunk: wait 0 -> barrier -> issue -> compute.
#define A_STAGE   16384
#define SLAB_P    296                  // floats per ci (4*68 + 24 pad); %32==8 -> frag LDS conflict-free
#define SLAB_R    68                   // floats per image row (4 pad left, data at 4..67)
#define SLAB_FLOATS (32 * SLAB_P)      // 9472
#define SLAB_BYTES (SLAB_FLOATS * 4)   // 37888 (16B multiple)
#define SMEM_BYTES (2 * A_STAGE + 2 * SLAB_BYTES)   // 108544 -> 2 CTAs/SM

#define CP16_CG(dst, src) \
    asm volatile("cp.async.cg.shared.global [%0], [%1], 16;" :: "r"(dst), "l"(src))
#define CP_COMMIT()   asm volatile("cp.async.commit_group;" ::: "memory")
#define CP_WAIT_ALL() asm volatile("cp.async.wait_group 0;" ::: "memory")

#define MMA_TF32(c, a, b0, b1)                                                 \
    asm volatile("mma.sync.aligned.m16n8k8.row.col.f32.tf32.tf32.f32 "         \
        "{%0,%1,%2,%3}, {%4,%5,%6,%7}, {%8,%9}, {%0,%1,%2,%3};"                \
        : "+f"((c)[0]), "+f"((c)[1]), "+f"((c)[2]), "+f"((c)[3])               \
        : "r"((a).x), "r"((a).y), "r"((a).z), "r"((a).w), "r"(b0), "r"(b1))

__global__ void __launch_bounds__(256, 2)
conv_mma(const float* __restrict__ x, const float* __restrict__ noise,
         const float* __restrict__ bias, const float* __restrict__ nwptr,
         float* __restrict__ out) {
    extern __shared__ __align__(16) char smem[];
    float* slabs = (float*)(smem + 2 * A_STAGE);   // S0, S1
    const uint32_t sbase = (uint32_t)__cvta_generic_to_shared(smem);

    const int tid  = threadIdx.x;
    const int w    = tid >> 5;
    const int lane = tid & 31;
    const int g    = lane >> 2;
    const int tig  = lane & 3;
    const int wm   = w >> 2;
    const int wn   = w & 3;

    const int y0     = blockIdx.x * 2;
    const int coBase = blockIdx.y * 128;
    const int b      = blockIdx.z;

    const float*  xb  = x + (size_t)b * (CIN * HH * WW);
    const float4* wa4 = (const float4*)g_wA + ((size_t)(b * 2 + blockIdx.y)) * (72 * 1024);

    // zero both slabs once (pads + out-of-range rows stay zero forever)
    for (int i = tid; i < 2 * SLAB_FLOATS; i += 256) slabs[i] = 0.f;

    float c[4][4][4];
#pragma unroll
    for (int mt = 0; mt < 4; mt++)
#pragma unroll
        for (int nt = 0; nt < 4; nt++)
#pragma unroll
            for (int i = 0; i < 4; i++) c[mt][nt][i] = 0.f;

    auto load_A = [&](int chunk, int buf) {
        const uint32_t abase = sbase + buf * A_STAGE;
        const float4* src4 = wa4 + chunk * 1024;
#pragma unroll
        for (int i = 0; i < 4; i++) {
            int idx = tid + 256 * i;
            CP16_CG(abase + idx * 16, src4 + idx);
        }
    };
    // async slab load: 128 (ci,row) rows x 16 float4 each = 8 cp16/thread
    auto load_slab = [&](int cig, int sb) {
        const uint32_t slbase = sbase + 2 * A_STAGE + sb * SLAB_BYTES;
#pragma unroll
        for (int i = 0; i < 8; i++) {
            int o   = tid + i * 256;
            int row = o >> 4;              // 0..127
            int f   = o & 15;              // float4 within row
            int ci  = row >> 2;
            int ry  = row & 3;
            int y   = y0 - 1 + ry;
            if ((unsigned)y < HH) {
                const float* src = xb + (size_t)(cig * 32 + ci) * (HH * WW) + y * WW + f * 4;
                CP16_CG(slbase + (ci * SLAB_P + ry * SLAB_R + 4 + f * 4) * 4, src);
            }
        }
    };

    __syncthreads();                       // slab zeroing visible before first loads
    load_A(0, 0);
    load_slab(0, 0);
    CP_COMMIT();

    // per-thread B fragment base (excl. ks/tap terms); data col = 4 + xx
    const int bfrag0 = tig * SLAB_P + (wn >> 1) * SLAB_R + (wn & 1) * 32 + g + 3;

    for (int chunk = 0; chunk < 72; chunk++) {
        CP_WAIT_ALL();
        __syncthreads();

        const int cig = chunk / 9;
        const int tap = chunk - 9 * cig;

        if (chunk + 1 < 72) {
            load_A(chunk + 1, (chunk + 1) & 1);
            if (tap == 0 && cig + 1 < 8) load_slab(cig + 1, (cig + 1) & 1);
            CP_COMMIT();
        }

        const int ky = tap / 3;
        const int kx = tap - ky * 3;
        const float* slab = slabs + (cig & 1) * SLAB_FLOATS;
        const float* bptr = slab + bfrag0 + ky * SLAB_R + kx;
        const uint4* Af = (const uint4*)(smem + (chunk & 1) * A_STAGE);

#pragma unroll
        for (int ks = 0; ks < 4; ks++) {
            uint4 a[4];
#pragma unroll
            for (int mt = 0; mt < 4; mt++)
                a[mt] = Af[((ks * 2 + wm) * 4 + mt) * 32 + lane];
            const float* bk = bptr + ks * (8 * SLAB_P);
            uint32_t b0[4], b1[4];
#pragma unroll
            for (int nt = 0; nt < 4; nt++) {
                b0[nt] = __float_as_uint(bk[nt * 8]);
                b1[nt] = __float_as_uint(bk[nt * 8 + 4 * SLAB_P]);
            }
#pragma unroll
            for (int mt = 0; mt < 4; mt++)
#pragma unroll
                for (int nt = 0; nt < 4; nt++)
                    MMA_TF32(c[mt][nt], a[mt], b0[nt], b1[nt]);
        }
    }

    // ---- epilogue: noise + bias + leaky_relu * sqrt(2)
    {
        const float nw = nwptr[0];
        const int y = y0 + (wn >> 1);
        const float* nzrow = noise + (size_t)b * (HH * WW) + y * WW;
#pragma unroll
        for (int mt = 0; mt < 4; mt++) {
            int co0 = coBase + wm * 64 + mt * 16 + g;
            float bv0 = bias[co0];
            float bv1 = bias[co0 + 8];
            float* o0 = out + (size_t)(b * COUT + co0) * (HH * WW) + y * WW;
            float* o1 = o0 + 8 * (HH * WW);
#pragma unroll
            for (int nt = 0; nt < 4; nt++) {
                int xc = (wn & 1) * 32 + nt * 8 + tig * 2;
                float2 nz = *(const float2*)(nzrow + xc);
                float nzx = nz.x * nw, nzy = nz.y * nw;
                float v0 = c[mt][nt][0] + nzx + bv0;
                float v1 = c[mt][nt][1] + nzy + bv0;
                float v2 = c[mt][nt][2] + nzx + bv1;
                float v3 = c[mt][nt][3] + nzy + bv1;
                v0 = (v0 > 0.f ? v0 : 0.2f * v0) * 1.41421356237309515f;
                v1 = (v1 > 0.f ? v1 : 0.2f * v1) * 1.41421356237309515f;
                v2 = (v2 > 0.f ? v2 : 0.2f * v2) * 1.41421356237309515f;
                v3 = (v3 > 0.f ? v3 : 0.2f * v3) * 1.41421356237309515f;
                *(float2*)(o0 + xc) = make_float2(v0, v1);
                *(float2*)(o1 + xc) = make_float2(v2, v3);
            }
        }
    }
}

// ---------------- launch ----------------
extern "C" void kernel_launch(void* const* d_in, const int* in_sizes, int n_in,
                              void* d_out, int out_size) {
    const float* x        = (const float*)d_in[0];
    const float* style    = (const float*)d_in[1];
    const float* noise    = (const float*)d_in[2];
    const float* weight   = (const float*)d_in[3];
    const float* style_w  = (const float*)d_in[4];
    const float* style_b  = (const float*)d_in[5];
    const float* bias     = (const float*)d_in[6];
    const float* nw       = (const float*)d_in[7];
    float* out = (float*)d_out;

    cudaFuncSetAttribute(conv_mma, cudaFuncAttributeMaxDynamicSharedMemorySize, SMEM_BYTES);

    fused1_kernel<<<272, 256>>>(style, style_w, style_b, weight);  // 1
    d_kernel<<<BATCH, 256>>>();                                    // 2
    wa_kernel<<<9216, 256>>>(weight);                              // 3
    conv_mma<<<dim3(32, 2, 16), 256, SMEM_BYTES>>>(x, noise, bias, nw, out);  // 4
}